// round 16
// baseline (speedup 1.0000x reference)
#include <cuda_runtime.h>
#include <cstdint>

// NGP hash-grid interpolation, R14: spatial counting-sort (res-32 bins) so
// warps process spatially adjacent points -> coarse-level corner gathers
// collapse to broadcasts within each LDG. Main kernel keeps the R11
// pair-lane layout (dim0 corner pairs coalesce into shared sectors).

constexpr int      LVL    = 16;
constexpr int      BLK    = 256;
constexpr uint32_t MASK19 = (1u << 19) - 1u;
constexpr uint32_t P1     = 2654435761u;
constexpr uint32_t P2     = 805459861u;

constexpr int NBINS = 32768;     // 32^3 spatial bins (5 bits/dim)
constexpr int MAXB  = 262144;

__device__ __constant__ float RES_C[LVL] = {
    16.f, 20.f, 25.f, 32.f, 40.f, 50.f, 64.f, 80.f,
    101.f, 128.f, 161.f, 203.f, 256.f, 322.f, 406.f, 512.f
};

__device__ uint32_t g_hist[NBINS];
__device__ uint32_t g_off[NBINS];
__device__ uint32_t g_sorted[MAXB];

__device__ __forceinline__ uint32_t point_bin(const float* __restrict__ x, int b)
{
    uint32_t c0 = min(31u, (uint32_t)(x[3 * b + 0] * 32.0f));
    uint32_t c1 = min(31u, (uint32_t)(x[3 * b + 1] * 32.0f));
    uint32_t c2 = min(31u, (uint32_t)(x[3 * b + 2] * 32.0f));
    return (c0 << 10) | (c1 << 5) | c2;
}

__global__ void zero_hist_kernel()
{
    int i = blockIdx.x * blockDim.x + threadIdx.x;
    if (i < NBINS) g_hist[i] = 0u;
}

__global__ void hist_kernel(const float* __restrict__ x, int B)
{
    int b = blockIdx.x * blockDim.x + threadIdx.x;
    if (b >= B) return;
    atomicAdd(&g_hist[point_bin(x, b)], 1u);
}

// Single-block exclusive scan over NBINS bins (1024 threads x 32 bins each).
__global__ void scan_kernel()
{
    __shared__ uint32_t s[1024];
    const int t = threadIdx.x;
    const int base = t * 32;

    uint32_t local[32];
    uint32_t sum = 0;
    #pragma unroll
    for (int i = 0; i < 32; ++i) {
        local[i] = sum;
        sum += g_hist[base + i];
    }
    s[t] = sum;
    __syncthreads();

    // Hillis-Steele inclusive scan over the 1024 chunk totals.
    for (int off = 1; off < 1024; off <<= 1) {
        uint32_t v = 0;
        if (t >= off) v = s[t - off];
        __syncthreads();
        if (t >= off) s[t] += v;
        __syncthreads();
    }
    const uint32_t chunk_base = s[t] - sum;   // exclusive
    #pragma unroll
    for (int i = 0; i < 32; ++i)
        g_off[base + i] = chunk_base + local[i];
}

__global__ void scatter_kernel(const float* __restrict__ x, int B)
{
    int b = blockIdx.x * blockDim.x + threadIdx.x;
    if (b >= B) return;
    uint32_t pos = atomicAdd(&g_off[point_bin(x, b)], 1u);
    g_sorted[pos] = (uint32_t)b;
}

__global__ __launch_bounds__(BLK)
void ngp_enc_kernel(const float* __restrict__ x,
                    const float* __restrict__ tables,
                    float* __restrict__ out,
                    int B)
{
    const int t = blockIdx.x * BLK + threadIdx.x;
    const int sIdx = t >> 1;       // sorted slot (2 lanes per point)
    const int p = t & 1;           // dim0 corner border for this lane
    if (sIdx >= B) return;
    const int b = (int)g_sorted[sIdx];

    const float x0 = x[3 * b + 0];
    const float x1 = x[3 * b + 1];
    const float x2 = x[3 * b + 2];

    // Each lane keeps the results of 8 levels: lane p owns levels [8p, 8p+8).
    float keep[16];

    #pragma unroll
    for (int l = 0; l < LVL; ++l) {
        const float r = RES_C[l];
        const float s0 = x0 * r, s1 = x1 * r, s2 = x2 * r;
        const float f0 = floorf(s0), f1 = floorf(s1), f2 = floorf(s2);
        const float fr0 = s0 - f0, fr1 = s1 - f1, fr2 = s2 - f2;
        const uint32_t g0 = (uint32_t)f0;
        const uint32_t g1 = (uint32_t)f1;
        const uint32_t g2 = (uint32_t)f2;

        const uint32_t h0  = g0 + (uint32_t)p;      // prime = 1
        const uint32_t h1a = g1 * P1, h1b = h1a + P1;
        const uint32_t h2a = g2 * P2, h2b = h2a + P2;

        const uint32_t i0 = (h0 ^ h1a ^ h2a) & MASK19;
        const uint32_t i1 = (h0 ^ h1b ^ h2a) & MASK19;
        const uint32_t i2 = (h0 ^ h1a ^ h2b) & MASK19;
        const uint32_t i3 = (h0 ^ h1b ^ h2b) & MASK19;

        const float2* __restrict__ tbl =
            reinterpret_cast<const float2*>(tables) + ((size_t)l << 19);

        const float2 t0 = __ldg(&tbl[i0]);
        const float2 t1 = __ldg(&tbl[i1]);
        const float2 t2 = __ldg(&tbl[i2]);
        const float2 t3 = __ldg(&tbl[i3]);

        const float w1a = 1.0f - fr1, w1b = fr1;
        const float w2a = 1.0f - fr2, w2b = fr2;
        const float w00 = w1a * w2a;
        const float w01 = w1b * w2a;
        const float w10 = w1a * w2b;
        const float w11 = w1b * w2b;

        float a0 = fmaf(w00, t0.x, fmaf(w01, t1.x, fmaf(w10, t2.x, w11 * t3.x)));
        float a1 = fmaf(w00, t0.y, fmaf(w01, t1.y, fmaf(w10, t2.y, w11 * t3.y)));
        const float w0 = p ? fr0 : (1.0f - fr0);
        a0 *= w0;
        a1 *= w0;

        a0 += __shfl_xor_sync(0xFFFFFFFFu, a0, 1);
        a1 += __shfl_xor_sync(0xFFFFFFFFu, a1, 1);

        if ((l >> 3) == p) {
            keep[2 * (l & 7) + 0] = a0;
            keep[2 * (l & 7) + 1] = a1;
        }
    }

    // Lane p stores floats [16p, 16p+16) of point b's 32-float output row.
    float4* o = reinterpret_cast<float4*>(out + (size_t)b * (2 * LVL) + p * 16);
    o[0] = make_float4(keep[0],  keep[1],  keep[2],  keep[3]);
    o[1] = make_float4(keep[4],  keep[5],  keep[6],  keep[7]);
    o[2] = make_float4(keep[8],  keep[9],  keep[10], keep[11]);
    o[3] = make_float4(keep[12], keep[13], keep[14], keep[15]);
}

extern "C" void kernel_launch(void* const* d_in, const int* in_sizes, int n_in,
                              void* d_out, int out_size)
{
    const float* x      = (const float*)d_in[0];
    const float* tables = (const float*)d_in[1];
    float* out          = (float*)d_out;

    const int B = in_sizes[0] / 3;

    zero_hist_kernel<<<(NBINS + 255) / 256, 256>>>();
    hist_kernel<<<(B + 255) / 256, 256>>>(x, B);
    scan_kernel<<<1, 1024>>>();
    scatter_kernel<<<(B + 255) / 256, 256>>>(x, B);

    const int nThreads = 2 * B;
    const int grid = (nThreads + BLK - 1) / BLK;
    ngp_enc_kernel<<<grid, BLK>>>(x, tables, out, B);
}